// round 17
// baseline (speedup 1.0000x reference)
#include <cuda_runtime.h>
#include <cuda_fp16.h>
#include <cstdint>

// Problem constants
#define Ln   128
#define Bn   1024
#define Hd   256
#define Dd   512
#define G3   1536
#define ODEH 128
#define INU  32
#define OUTd 16
#define ROWS (Ln * Bn)  // 131072
#define NBLK 128        // persistent grid, 1 CTA/SM via smem; 16 clusters of 8

typedef __half fp16;

// ---------------- scratch (device globals; no allocs allowed) ----------------
__device__ fp16  g_Xh [(size_t)ROWS * Dd];     // embeddings fp16 (m-major)
__device__ float g_giT[(size_t)Ln * G3 * Bn];  // gi TRANSPOSED [t][gate*512+d][b]
__device__ float g_hnT[(size_t)Ln * Dd * Bn];  // hn history TRANSPOSED [t][d][b]
__device__ float g_tmpT[(size_t)Dd * Bn];      // GRU out TRANSPOSED [d][b]
__device__ fp16  g_hh [Bn * Dd];               // current h fp16 (m-major)
__device__ fp16  g_Wih[G3 * Dd];               // W_ih fp16
__device__ fp16  g_Whh[G3 * Dd];               // W_hh fp16

// ---------------- smem map ----------------
// W: 3 regions (one per gate), each 64 rows x 512 k fp16, 1024B/row,
//    16B-slot XOR swizzle (slot ^ (n&7)) -> conflict-free ldmatrix.
#define W_REGION 65536
#define SW_BYTES (3 * W_REGION)           // 196608
#define OFF_SA   SW_BYTES
// A double buffer: 2 x 8192 (NS=1)
#define SMEM_TOTAL (SW_BYTES + 32768)     // 229376 (ODE overlay also lives here)

// ---------------- asm helpers ----------------
__device__ __forceinline__ uint32_t smem_to_u32(const void* p) {
    uint32_t a;
    asm("{ .reg .u64 t; cvta.to.shared.u64 t, %1; cvt.u32.u64 %0, t; }" : "=r"(a) : "l"(p));
    return a;
}
__device__ __forceinline__ void mma16816(float* c, const unsigned* a, const unsigned* b) {
    asm volatile(
        "mma.sync.aligned.m16n8k16.row.col.f32.f16.f16.f32 "
        "{%0,%1,%2,%3}, {%4,%5,%6,%7}, {%8,%9}, {%0,%1,%2,%3};\n"
        : "+f"(c[0]), "+f"(c[1]), "+f"(c[2]), "+f"(c[3])
        : "r"(a[0]), "r"(a[1]), "r"(a[2]), "r"(a[3]), "r"(b[0]), "r"(b[1]));
}
__device__ __forceinline__ void ldsm4(uint32_t addr, uint32_t* r) {
    asm volatile("ldmatrix.sync.aligned.m8n8.x4.shared.b16 {%0,%1,%2,%3}, [%4];"
                 : "=r"(r[0]), "=r"(r[1]), "=r"(r[2]), "=r"(r[3]) : "r"(addr));
}
#define CP16(dst, src) asm volatile("cp.async.cg.shared.global [%0], [%1], 16;" :: "r"(dst), "l"(src))
#define CPCOMMIT()     asm volatile("cp.async.commit_group;" ::: "memory")
#define CPWAIT0()      asm volatile("cp.async.wait_group 0;" ::: "memory")
// cluster barrier: arrive has release, wait has acquire semantics (cluster scope
// covers global-memory handoff between the 8 CTAs of the group).
#define CLUSTER_SYNC() do { \
    asm volatile("barrier.cluster.arrive.aligned;" ::: "memory"); \
    asm volatile("barrier.cluster.wait.aligned;" ::: "memory"); \
} while (0)

// ---------------- init ----------------
__global__ void k_zero() {
    int i = blockIdx.x * 1024 + threadIdx.x;   // 512x1024 = Bn*Dd
    g_hnT[i] = 0.0f;
    g_hh[i] = __float2half(0.0f);
}

// fused: converts W_ih (y=0) and W_hh (y=1)
__global__ void k_wconv(const float* __restrict__ Wa, fp16* __restrict__ Wao,
                        const float* __restrict__ Wb, fp16* __restrict__ Wbo) {
    size_t i = (size_t)blockIdx.x * 512 + threadIdx.x;
    if (blockIdx.y == 0) Wao[i] = __float2half(Wa[i]);
    else                 Wbo[i] = __float2half(Wb[i]);
}

// ---------------- embeddings: 1024 blocks x 128 rows, weights staged once ----------------
__global__ __launch_bounds__(256) void k_embed(
    const float* __restrict__ ext, const float* __restrict__ obs,
    const float* __restrict__ Wu, const float* __restrict__ bu,
    const float* __restrict__ Wx, const float* __restrict__ bx)
{
    __shared__ float sWu[INU * Hd];    // 32 KB  (k-major: sWu[k*256+col])
    __shared__ float sWx[OUTd * Hd];   // 16 KB
    __shared__ float sIn[128 * INU];   // 16 KB
    __shared__ float sOb[128 * OUTd];  //  8 KB
    const int row0 = blockIdx.x * 128;
    const int tid = threadIdx.x;
    #pragma unroll 4
    for (int i = tid; i < INU * Hd; i += 256) sWu[i] = Wu[i];
    #pragma unroll 4
    for (int i = tid; i < OUTd * Hd; i += 256) sWx[i] = Wx[i];
    #pragma unroll 4
    for (int i = tid; i < 128 * INU; i += 256) {
        int r = i >> 5, k = i & 31;
        sIn[i] = ext[(size_t)(row0 + r) * (INU + 1) + k];
    }
    #pragma unroll 4
    for (int i = tid; i < 128 * OUTd; i += 256) {
        int r = i >> 4, k = i & 15;
        sOb[i] = obs[(size_t)(row0 + r) * OUTd + k];
    }
    __syncthreads();
    const float bu_t = bu[tid];
    const float bx_t = bx[tid];
    for (int r = 0; r < 128; r++) {
        float au = bu_t;
        #pragma unroll
        for (int k = 0; k < INU; k++) au += sIn[r * INU + k] * sWu[k * Hd + tid];
        float ax = bx_t;
        #pragma unroll
        for (int k = 0; k < OUTd; k++) ax += sOb[r * OUTd + k] * sWx[k * Hd + tid];
        size_t base = (size_t)(row0 + r) * Dd;
        g_Xh[base + tid]      = __float2half(tanhf(au));
        g_Xh[base + Hd + tid] = __float2half(tanhf(ax));
    }
}

// ---------------- W loader: 3 regions, 64 rows, 1024B/row, 16B-slot XOR swizzle ----------------
__device__ void load_Wsw(const fp16* __restrict__ W, int d0, char* sW, int tid) {
    #pragma unroll 4
    for (int it = 0; it < 48; it++) {
        int flat = tid + it * 256;            // uint4 index, 0..12287
        int g = flat >> 12;                   // region 0..2 (gate)
        int rem = flat & 4095;
        int n    = rem >> 6;                  // row 0..63
        int slot = rem & 63;                  // 16B slot (8 fp16)
        uint4 v = *(const uint4*)(W + (size_t)(g * Dd + d0 + n) * Dd + slot * 8);
        *(uint4*)(sW + g * W_REGION + n * 1024 + ((slot ^ (n & 7)) << 4)) = v;
    }
}

// ---------------- GEMM: C[64m x 192n] = A[64,512] @ Wslice^T (single fp16 term) ----------------
// 64k chunks (two 32k sub-chunks), double buffered.
__device__ __forceinline__ void gemm_tile(
    const fp16* __restrict__ Ah,
    uint32_t sAu, float acc[3][2][2][4], int tid,
    uint32_t aBase, uint32_t aSlotL, uint32_t aSw,
    uint32_t bBase, uint32_t bKh, uint32_t bSw)
{
    const uint32_t BUFSZ = 8192u;
    #pragma unroll
    for (int g = 0; g < 3; g++)
        #pragma unroll
        for (int i2 = 0; i2 < 2; i2++)
            #pragma unroll
            for (int j2 = 0; j2 < 2; j2++)
                #pragma unroll
                for (int e = 0; e < 4; e++) acc[g][i2][j2][e] = 0.0f;

    // per-thread fill slots (2 x 16B per buffer); layout: [sub(2)][m(64)][slot(4) swizzled]
    uint32_t fd[2]; const fp16* fs[2];
    #pragma unroll
    for (int i = 0; i < 2; i++) {
        int flat = tid + i * 256;                 // 0..511
        int slot = flat & 3;
        int m = (flat >> 2) & 63;
        int sub = flat >> 8;
        fd[i] = sAu + (uint32_t)sub * 4096u + (uint32_t)m * 64u
                + ((uint32_t)(slot ^ ((m >> 1) & 3)) << 4);
        fs[i] = Ah + (size_t)m * Dd + sub * 32 + slot * 8;
    }
    #pragma unroll
    for (int i = 0; i < 2; i++) CP16(fd[i], fs[i]);
    CPCOMMIT();

    for (int c = 0; c < 8; c++) {                 // 8 chunks x 64 k
        CPWAIT0();
        __syncthreads();
        if (c < 7) {
            uint32_t nb = ((uint32_t)(c + 1) & 1u) * BUFSZ;
            #pragma unroll
            for (int i = 0; i < 2; i++) CP16(fd[i] + nb, fs[i] + (c + 1) * 64);
            CPCOMMIT();
        }
        uint32_t ab = aBase + ((uint32_t)(c & 1)) * BUFSZ;
        #pragma unroll
        for (int sub = 0; sub < 2; sub++) {
            uint32_t absub = ab + (uint32_t)sub * 4096u;
            #pragma unroll
            for (int ks8 = 0; ks8 <= 2; ks8 += 2) {
                uint32_t afr[2][4];
                #pragma unroll
                for (int i2 = 0; i2 < 2; i2++)
                    ldsm4(absub + i2 * 1024u + (((aSlotL + ks8) ^ aSw) << 4), afr[i2]);
                uint32_t bfr[3][4];
                uint32_t bslot = (uint32_t)(c * 8 + sub * 4 + ks8) + bKh;
                #pragma unroll
                for (int g = 0; g < 3; g++)
                    ldsm4(bBase + g * W_REGION + ((bslot ^ bSw) << 4), bfr[g]);
                #pragma unroll
                for (int g = 0; g < 3; g++)
                    #pragma unroll
                    for (int i2 = 0; i2 < 2; i2++)
                        #pragma unroll
                        for (int j2 = 0; j2 < 2; j2++)
                            mma16816(acc[g][i2][j2], afr[i2], &bfr[g][j2 * 2]);
            }
        }
    }
}

// ---------------- THE persistent kernel (clusters of 8 = one mg group) ----------------
__global__ void __launch_bounds__(256, 1) __cluster_dims__(8, 1, 1) k_persist(
    const float* __restrict__ ext,
    const float* __restrict__ bih, const float* __restrict__ bhh,
    const float* __restrict__ W1, const float* __restrict__ b1,
    const float* __restrict__ W2, const float* __restrict__ b2)
{
    extern __shared__ char smem[];
    uint32_t sWu_ = smem_to_u32(smem);
    uint32_t sAu = sWu_ + OFF_SA;
    float* s_h  = (float*)(smem + OFF_SA);            // [8][260]   (overlay on sA)
    float* s_zp = (float*)(smem + OFF_SA + 8320);     // [2][8][132] partials -> z in [0]
    float* s_c  = (float*)(smem + OFF_SA + 16768);    // [8][130]
    float* s_dt = (float*)(smem + OFF_SA + 20928);    // [8]

    const int tid = threadIdx.x;
    const int wid = tid >> 5, lane = tid & 31;
    const int bid = blockIdx.x;
    const int dtile = bid & 7, mg = bid >> 3;         // 8 d-tiles x 64, 16 m-groups x 64
    const int d0 = dtile * 64;
    const int m0ode = bid * 8;
    const int warp_m = wid >> 2, warp_n = wid & 3;    // 2 x 4 warp grid
    const int q = lane >> 2, tp = lane & 3;

    // ldmatrix per-lane constants
    const int aRow = warp_m * 32 + (lane & 7) + ((lane >> 3) & 1) * 8;
    const uint32_t aBase = sAu + (uint32_t)aRow * 64;
    const uint32_t aSlotL = (uint32_t)(lane >> 4);
    const uint32_t aSw = (uint32_t)((aRow >> 1) & 3);
    const int bRowN = warp_n * 16 + (lane & 7) + ((lane >> 4) & 1) * 8;
    const uint32_t bBase = sWu_ + (uint32_t)bRowN * 1024;
    const uint32_t bKh = (uint32_t)((lane >> 3) & 1);
    const uint32_t bSw = (uint32_t)(bRowN & 7);

    float acc[3][2][2][4];

    // per-thread bias values (d depends only on j2, eo)
    float bI[3][2][2], bH[3][2][2];
    #pragma unroll
    for (int g = 0; g < 3; g++)
        #pragma unroll
        for (int j2 = 0; j2 < 2; j2++)
            #pragma unroll
            for (int eo = 0; eo < 2; eo++) {
                int d = d0 + warp_n * 16 + j2 * 8 + tp * 2 + eo;
                bI[g][j2][eo] = bih[g * Dd + d];
                bH[g][j2][eo] = bhh[g * Dd + d];
            }

    // ======== Phase 1: gi = X @ W_ih^T + b_ih ========
    load_Wsw(g_Wih, d0, smem, tid);
    __syncthreads();
    for (int t = 0; t < 127; t++) {
        const fp16* Ah = g_Xh + ((size_t)t * Bn + mg * 64) * Dd;
        gemm_tile(Ah, sAu, acc, tid, aBase, aSlotL, aSw, bBase, bKh, bSw);
        float* giT = g_giT + (size_t)t * G3 * Bn;
        #pragma unroll
        for (int i2 = 0; i2 < 2; i2++)
            #pragma unroll
            for (int j2 = 0; j2 < 2; j2++)
                #pragma unroll
                for (int e = 0; e < 4; e++) {
                    int b = mg * 64 + warp_m * 32 + i2 * 16 + q + (e >> 1) * 8;
                    int d = d0 + warp_n * 16 + j2 * 8 + tp * 2 + (e & 1);
                    #pragma unroll
                    for (int g = 0; g < 3; g++)
                        giT[(size_t)(g * Dd + d) * Bn + b] = acc[g][i2][j2][e] + bI[g][j2][e & 1];
                }
    }

    // ======== Phase 2: recurrent loop (cluster-local synchronization only) ========
    __syncthreads();                      // all warps done reading W_ih smem
    load_Wsw(g_Whh, d0, smem, tid);
    __syncthreads();

    const bool is_cpart = (d0 >= Hd);     // this block's d-tile lies in the c passthrough range

    for (int t = 0; t < 127; t++) {
        gemm_tile(g_hh + (size_t)mg * 64 * Dd, sAu, acc, tid, aBase, aSlotL, aSw, bBase, bKh, bSw);
        // fused GRU gates epilogue -> g_tmpT (+ direct hnT1 write for c-part)
        const float* giT = g_giT + (size_t)t * G3 * Bn;
        const float* hpT = g_hnT + (size_t)t * Dd * Bn;
        float* hnT1 = g_hnT + (size_t)(t + 1) * Dd * Bn;
        #pragma unroll
        for (int i2 = 0; i2 < 2; i2++)
            #pragma unroll
            for (int j2 = 0; j2 < 2; j2++)
                #pragma unroll
                for (int e = 0; e < 4; e++) {
                    int b = mg * 64 + warp_m * 32 + i2 * 16 + q + (e >> 1) * 8;
                    int d = d0 + warp_n * 16 + j2 * 8 + tp * 2 + (e & 1);
                    float gR = acc[0][i2][j2][e] + bH[0][j2][e & 1];
                    float gZ = acc[1][i2][j2][e] + bH[1][j2][e & 1];
                    float gN = acc[2][i2][j2][e] + bH[2][j2][e & 1];
                    float giR = __ldcg(&giT[(size_t)d * Bn + b]);
                    float giZ = __ldcg(&giT[(size_t)(Dd + d) * Bn + b]);
                    float giN = __ldcg(&giT[(size_t)(2 * Dd + d) * Bn + b]);
                    float r = 1.0f / (1.0f + __expf(-(giR + gR)));
                    float z = 1.0f / (1.0f + __expf(-(giZ + gZ)));
                    float nn = tanhf(giN + r * gN);
                    float hp = __ldcg(&hpT[(size_t)d * Bn + b]);
                    float val = (1.0f - z) * nn + z * hp;
                    g_tmpT[(size_t)d * Bn + b] = val;
                    if (is_cpart)                              // c passthrough: hn[t+1] = GRU out
                        hnT1[(size_t)d * Bn + b] = val;
                }
        CLUSTER_SYNC();                   // group's epilogues done

        // ---- ODE MLP + Euler for rows m0ode..m0ode+7 ----
        #pragma unroll
        for (int i = 0; i < 8; i++) {
            int idx = tid + i * 256;
            int r = idx & 7, cc = idx >> 3;           // cc 0..255
            s_h[r * 260 + cc] = __ldcg(&g_tmpT[(size_t)cc * Bn + m0ode + r]);
        }
        if (tid < 8) s_dt[tid] = ext[((size_t)t * Bn + m0ode + tid) * (INU + 1) + INU];
        __syncthreads();
        {   // z = tanh(h @ W1 + b1), k-split across warp halves (W1 read exactly once)
            int col = tid & 127, half = tid >> 7;
            float a[8];
            #pragma unroll
            for (int r = 0; r < 8; r++) a[r] = 0.0f;
            const int kb = half * 128;
            #pragma unroll 4
            for (int k = 0; k < 128; k++) {
                float w = W1[(kb + k) * ODEH + col];
                #pragma unroll
                for (int r = 0; r < 8; r++) a[r] += s_h[r * 260 + kb + k] * w;
            }
            #pragma unroll
            for (int r = 0; r < 8; r++) s_zp[half * 1056 + r * 132 + col] = a[r];
        }
        __syncthreads();
        #pragma unroll
        for (int i = 0; i < 4; i++) {                 // combine halves + tanh (into s_zp[0])
            int idx = tid + i * 256;
            int r = idx >> 7, c = idx & 127;
            s_zp[r * 132 + c] = tanhf(s_zp[r * 132 + c] + s_zp[1056 + r * 132 + c] + b1[c]);
        }
        __syncthreads();
        float hnew[8];
        {   // f = z @ W2 + b2 ; hnew = h + dt*f ; write g_hh (h part, m-major)
            int col = tid;
            float f[8];
            float bb = b2[col];
            #pragma unroll
            for (int r = 0; r < 8; r++) f[r] = bb;
            #pragma unroll 4
            for (int k = 0; k < ODEH; k++) {
                float w = W2[k * Hd + col];
                #pragma unroll
                for (int r = 0; r < 8; r++) f[r] += s_zp[r * 132 + k] * w;
            }
            #pragma unroll
            for (int r = 0; r < 8; r++) {
                hnew[r] = s_h[r * 260 + col] + s_dt[r] * f[r];
                g_hh[(size_t)(m0ode + r) * Dd + col] = __float2half(hnew[r]);
                s_h[r * 260 + col] = hnew[r];         // same-thread same-address: no sync needed
            }
        }
        __syncthreads();
        #pragma unroll
        for (int i = 0; i < 8; i++) {                 // h part of hn[t+1] (hnT1 from loop top)
            int idx = tid + i * 256;
            int r = idx & 7, cc = idx >> 3;
            hnT1[(size_t)cc * Bn + m0ode + r] = s_h[r * 260 + cc];
        }
        #pragma unroll
        for (int ch = 0; ch < 2; ch++) {              // c -> g_hh fp16 (hnT1 done by epilogue)
            int cbase = Hd + ch * 128;
            #pragma unroll
            for (int i = 0; i < 4; i++) {
                int idx = tid + i * 256;
                int r = idx & 7, cl = idx >> 3;
                s_c[r * 130 + cl] = __ldcg(&g_tmpT[(size_t)(cbase + cl) * Bn + m0ode + r]);
            }
            __syncthreads();
            #pragma unroll
            for (int i = 0; i < 4; i++) {
                int idx = tid + i * 256;
                int r = idx >> 7, cl = idx & 127;
                g_hh[(size_t)(m0ode + r) * Dd + cbase + cl] = __float2half(s_c[r * 130 + cl]);
            }
            __syncthreads();
        }
        CLUSTER_SYNC();                   // group's ODE done -> next GEMM may read g_hh
    }
}

// ---------------- output projection ----------------
__global__ __launch_bounds__(256) void k_out(
    const float* __restrict__ WLy, const float* __restrict__ bLy,
    float* __restrict__ out)
{
    __shared__ float s_w[Dd * OUTd];   // 32 KB
    int t = blockIdx.x >> 3;
    int b0 = (blockIdx.x & 7) * 128;
    int tid = threadIdx.x;
    #pragma unroll
    for (int i = 0; i < 32; i++) s_w[tid + i * 256] = WLy[tid + i * 256];
    __syncthreads();
    int b = b0 + (tid >> 1);
    int oh = (tid & 1) * 8;
    const float* hp = g_hnT + (size_t)t * Dd * Bn;
    float a[8];
    #pragma unroll
    for (int j = 0; j < 8; j++) a[j] = bLy[oh + j];
    #pragma unroll 4
    for (int k = 0; k < Dd; k++) {
        float v = __ldg(&hp[(size_t)k * Bn + b]);
        #pragma unroll
        for (int j = 0; j < 8; j++) a[j] += v * s_w[k * OUTd + oh + j];
    }
    float* op = out + ((size_t)t * Bn + b) * OUTd + oh;
    *(float4*)(op)     = make_float4(a[0], a[1], a[2], a[3]);
    *(float4*)(op + 4) = make_float4(a[4], a[5], a[6], a[7]);
}

// ---------------- launch ----------------
extern "C" void kernel_launch(void* const* d_in, const int* in_sizes, int n_in,
                              void* d_out, int out_size)
{
    const float* ext = (const float*)d_in[0];
    const float* obs = (const float*)d_in[1];
    const float* Wu  = (const float*)d_in[2];
    const float* bu  = (const float*)d_in[3];
    const float* Wx  = (const float*)d_in[4];
    const float* bx  = (const float*)d_in[5];
    const float* Wih = (const float*)d_in[6];
    const float* Whh = (const float*)d_in[7];
    const float* bih = (const float*)d_in[8];
    const float* bhh = (const float*)d_in[9];
    const float* W1  = (const float*)d_in[10];
    const float* b1  = (const float*)d_in[11];
    const float* W2  = (const float*)d_in[12];
    const float* b2  = (const float*)d_in[13];
    const float* WLy = (const float*)d_in[14];
    const float* bLy = (const float*)d_in[15];
    float* out = (float*)d_out;

    fp16 *p_Wih, *p_Whh;
    cudaGetSymbolAddress((void**)&p_Wih, g_Wih);
    cudaGetSymbolAddress((void**)&p_Whh, g_Whh);

    cudaFuncSetAttribute(k_persist, cudaFuncAttributeMaxDynamicSharedMemorySize, SMEM_TOTAL);

    k_zero<<<512, 1024>>>();
    k_wconv<<<dim3(G3, 2), 512>>>(Wih, p_Wih, Whh, p_Whh);
    k_embed<<<ROWS / 128, 256>>>(ext, obs, Wu, bu, Wx, bx);

    k_persist<<<NBLK, 256, SMEM_TOTAL>>>(ext, bih, bhh, W1, b1, W2, b2);

    k_out<<<Ln * 8, 256>>>(WLy, bLy, out);
}